// round 15
// baseline (speedup 1.0000x reference)
#include <cuda_runtime.h>
#include <cuda_fp16.h>

// ---------------- problem constants ----------------
#define BB   2
#define CC   24
#define KQ   7
#define KK   49
#define HH   256
#define WW   256
#define CO   1176          // CC*KK
#define PLANE 65536
#define NPIX  131072

#define GC   6             // channels per L2-resident diffusion group (77MB < 126MB L2)
#define NGRP (CC / GC)     // 4 groups

#define LOG2E 1.4426950408889634f

// ---------------- device scratch ----------------
__device__ __half g_E[(size_t)CO * NPIX];   // unnormalized exp(logits), fp16, PLANE-MAJOR
__device__ float g_Spart[(size_t)CC * NPIX];
__device__ float g_Sinv[NPIX];
__device__ float g_lat[BB * CC * PLANE];
__device__ float g_dA[BB * CC * PLANE];     // raw (unnormalized) diffusion values
__device__ float g_dB[BB * CC * PLANE];

__device__ __forceinline__ float rcpf(float x) {
    float r; asm("rcp.approx.f32 %0, %1;" : "=f"(r) : "f"(x)); return r;
}
__device__ __forceinline__ __half2 ex2h2(__half2 x) {
    unsigned int xi = *reinterpret_cast<unsigned int*>(&x);
    unsigned int ri;
    asm("ex2.approx.f16x2 %0, %1;" : "=r"(ri) : "r"(xi));
    __half2 r;
    *reinterpret_cast<unsigned int*>(&r) = ri;
    return r;
}

// ================= K1: depth_latent = conv3x3(depth; 1 -> 24) =================
__global__ void k_lat(const float* __restrict__ depth,
                      const float* __restrict__ w_dp,
                      const float* __restrict__ b_dp) {
    __shared__ float sD[3][WW + 2];
    __shared__ float sW[CC * 9];
    __shared__ float sB[CC];
    const int bid = blockIdx.x;
    const int b = bid >> 8, y = bid & 255;
    const int tid = threadIdx.x;

    for (int i = tid; i < CC * 9; i += blockDim.x) sW[i] = w_dp[i];
    if (tid < CC) sB[tid] = b_dp[tid];

    const float* dp = depth + (size_t)b * PLANE;
    for (int r = 0; r < 3; r++) {
        const int yy = y + r - 1;
        for (int xx = tid; xx < WW + 2; xx += blockDim.x) {
            const int gx = xx - 1;
            sD[r][xx] = (yy >= 0 && yy < HH && gx >= 0 && gx < WW) ? dp[yy * WW + gx] : 0.f;
        }
    }
    __syncthreads();

    float p[9];
#pragma unroll
    for (int r = 0; r < 3; r++)
#pragma unroll
        for (int cx = 0; cx < 3; cx++) p[r * 3 + cx] = sD[r][tid + cx];

    for (int co = 0; co < CC; co++) {
        float acc = sB[co];
#pragma unroll
        for (int j = 0; j < 9; j++) acc = fmaf(sW[co * 9 + j], p[j], acc);
        g_lat[((size_t)(b * CC + co) * HH + y) * WW + tid] = acc;
    }
}

// ================= K2: logits conv + exp + partial sums + FUSED ITERATION 1 ==========
#define SR2 (WW + 12)
__global__ __launch_bounds__(128) void k_softmax(const float* __restrict__ tex,
                                                 const float* __restrict__ w_kp,
                                                 const float* __restrict__ b_kp) {
    __shared__ __align__(16) __half sWh[KK * 32];     // 27 weights + 5 zero-pad per output
    __shared__ __half2 sBh[KK];
    __shared__ __half sTh[3][4][WW + 2];
    __shared__ __align__(16) __half hL[10][SR2];      // lat rows y0-3..y0+6
    __shared__ __align__(16) __half hLO[10][SR2];     // hLO[r][xx] = hL[r][xx+1]

    const int bid = blockIdx.x;
    const int c = blockIdx.y;
    const int b = bid >> 7;
    const int y0 = (bid & 127) * 2;
    const int tid = threadIdx.x;
    const int ri = tid >> 6;
    const int x0 = (tid & 63) * 4;

    for (int i = tid; i < KK * 32; i += 128) {
        const int o = i >> 5, j = i & 31;
        const float w = (j < 27) ? w_kp[(size_t)(c * KK + o) * 27 + j] * LOG2E : 0.f;
        sWh[i] = __float2half_rn(w);
    }
    if (tid < KK) {
        const __half h = __float2half_rn(b_kp[c * KK + tid] * LOG2E);
        sBh[tid] = __halves2half2(h, h);
    }

    for (int ch = 0; ch < 3; ch++) {
        const float* tp = tex + (size_t)(b * 3 + ch) * PLANE;
        for (int rr = 0; rr < 4; rr++) {
            const int yy = y0 + rr - 1;
            for (int xx = tid; xx < WW + 2; xx += 128) {
                const int gx = xx - 1;
                const float v = (yy >= 0 && yy < HH && gx >= 0 && gx < WW) ? tp[yy * WW + gx] : 0.f;
                sTh[ch][rr][xx] = __float2half_rn(v);
            }
        }
    }

    {
        const float* lp = g_lat + (size_t)(b * CC + c) * PLANE;
        for (int r = 0; r < 10; r++) {
            const int yy = y0 + r - 3;
            for (int xx = tid; xx < WW + 8; xx += 128) {
                const int gx = xx - 3;
                const float v = (yy >= 0 && yy < HH && gx >= 0 && gx < WW) ? lp[yy * WW + gx] : 0.f;
                const __half h = __float2half_rn(v);
                hL[r][xx] = h;
                if (xx > 0) hLO[r][xx - 1] = h;
            }
        }
    }
    __syncthreads();

    __half2 PA[28], PB[28];
#pragma unroll
    for (int ch = 0; ch < 3; ch++)
#pragma unroll
        for (int r = 0; r < 3; r++) {
            __half v[6];
#pragma unroll
            for (int k = 0; k < 6; k++) v[k] = sTh[ch][ri + r][x0 + k];
#pragma unroll
            for (int cx = 0; cx < 3; cx++) {
                const int j = ch * 9 + r * 3 + cx;
                PA[j] = __halves2half2(v[cx], v[cx + 1]);
                PB[j] = __halves2half2(v[cx + 2], v[cx + 3]);
            }
        }
    PA[27] = __float2half2_rn(0.f);
    PB[27] = __float2half2_rn(0.f);

    float S0 = 0.f, S1 = 0.f, S2 = 0.f, S3 = 0.f;
    float dv0 = 0.f, dv1 = 0.f, dv2 = 0.f, dv3 = 0.f;
    const size_t pixbase = (size_t)b * PLANE + (size_t)(y0 + ri) * WW + x0;
    const __half2 Z2 = __float2half2_rn(0.f);

#pragma unroll 1
    for (int dx = 0; dx < KQ; dx++) {
        const __half* rowp = (dx & 1) ? &hLO[0][0] : &hL[0][0];
        const int xb = x0 + dx - (dx & 1);
        __half2 dacA = Z2, dacB = Z2;
#pragma unroll
        for (int dy = 0; dy < KQ; dy++) {
            const int ol = dy * KQ + dx;
            const uint4* wq = reinterpret_cast<const uint4*>(&sWh[ol * 32]);
            const __half2 bia = sBh[ol];
            __half2 wv[16];
            *reinterpret_cast<uint4*>(&wv[0])  = wq[0];
            *reinterpret_cast<uint4*>(&wv[4])  = wq[1];
            *reinterpret_cast<uint4*>(&wv[8])  = wq[2];
            *reinterpret_cast<uint4*>(&wv[12]) = wq[3];
            __half2 aA[4], aB[4];
            aA[0] = bia; aA[1] = Z2; aA[2] = Z2; aA[3] = Z2;
            aB[0] = bia; aB[1] = Z2; aB[2] = Z2; aB[3] = Z2;
#pragma unroll
            for (int j = 0; j < 28; j++) {
                const __half2 wj = (j & 1) ? __high2half2(wv[j >> 1]) : __low2half2(wv[j >> 1]);
                const int k = j & 3;
                aA[k] = __hfma2(wj, PA[j], aA[k]);
                aB[k] = __hfma2(wj, PB[j], aB[k]);
            }
            const __half2 a0 = __hadd2(__hadd2(aA[0], aA[1]), __hadd2(aA[2], aA[3]));
            const __half2 b0 = __hadd2(__hadd2(aB[0], aB[1]), __hadd2(aB[2], aB[3]));
            const __half2 eA = ex2h2(a0);
            const __half2 eB = ex2h2(b0);
            const float2 fA = __half22float2(eA);
            const float2 fB = __half22float2(eB);
            S0 += fA.x; S1 += fA.y; S2 += fB.x; S3 += fB.y;
            uint2 st;
            st.x = *reinterpret_cast<const unsigned int*>(&eA);
            st.y = *reinterpret_cast<const unsigned int*>(&eB);
            *reinterpret_cast<uint2*>(&g_E[(size_t)(c * KK + ol) * NPIX + pixbase]) = st;
            const __half* rp = rowp + (ri + dy) * SR2 + xb;
            __half2 p1, p2;
            *reinterpret_cast<unsigned int*>(&p1) = *reinterpret_cast<const unsigned int*>(rp);
            *reinterpret_cast<unsigned int*>(&p2) = *reinterpret_cast<const unsigned int*>(rp + 2);
            dacA = __hfma2(eA, p1, dacA);
            dacB = __hfma2(eB, p2, dacB);
        }
        const float2 fa = __half22float2(dacA);
        const float2 fb = __half22float2(dacB);
        dv0 += fa.x; dv1 += fa.y; dv2 += fb.x; dv3 += fb.y;
    }
    float4 ps;
    ps.x = S0; ps.y = S1; ps.z = S2; ps.w = S3;
    *reinterpret_cast<float4*>(&g_Spart[(size_t)c * NPIX + pixbase]) = ps;
    float4 dd;
    dd.x = dv0; dd.y = dv1; dd.z = dv2; dd.w = dv3;
    *reinterpret_cast<float4*>(&g_dA[(size_t)(b * CC + c) * PLANE + (size_t)(y0 + ri) * WW + x0]) = dd;
}

// ================= K2b: reduce 24 partials -> 1/S =================
__global__ void k_sinv() {
    const int idx = blockIdx.x * 256 + threadIdx.x;
    float s = 0.f;
#pragma unroll
    for (int c = 0; c < CC; c++) s += g_Spart[(size_t)c * NPIX + idx];
    g_Sinv[idx] = rcpf(s);
}

// ================= K3..: one diffusion iteration over a 6-channel group ==========
// Tile: 8 rows x 128 px -> grid (2*HH/8=64, GC, BB) = 768 blocks (1.3 waves).
// Thread: ri = tid>>5 (row 0..7), xl = (tid&31)*4 (4-px quad). One pass.
#define RROWS 8
#define TILEW 128
#define SROW2 144          // 134 needed; padded to 16B multiple
__global__ __launch_bounds__(256, 4) void k_diff(int srcSel, int dstSel, int c0) {
    __shared__ __align__(16) __half hE[RROWS + 6][SROW2];
    __shared__ __align__(16) __half hO[RROWS + 6][SROW2];
    const int tid = threadIdx.x;
    const int tx = blockIdx.x & 1;              // x-tile (0/1)
    const int ty = blockIdx.x >> 1;             // y-tile (0..31)
    const int c = c0 + blockIdx.y;
    const int b = blockIdx.z;
    const int y0 = ty * RROWS;
    const int xbase = tx * TILEW;
    const int ri = tid >> 5;                    // 0..7
    const int xl = (tid & 31) * 4;              // 0..124

    const float* src = (srcSel == 1) ? g_dA : g_dB;
    float* dst = (dstSel == 1) ? g_dA : g_dB;

    const float* sp = src + (size_t)(b * CC + c) * PLANE;
    const float* sip = g_Sinv + (size_t)b * PLANE;
    for (int r = 0; r < RROWS + 6; r++) {
        const int yy = y0 + r - 3;
        for (int xx = tid; xx < TILEW + 6; xx += 256) {
            const int gx = xbase + xx - 3;
            float v = 0.f;
            if (yy >= 0 && yy < HH && gx >= 0 && gx < WW) {
                const int q = yy * WW + gx;
                v = sp[q] * sip[q];          // deferred normalization at consumption
            }
            const __half h = __float2half_rn(v);
            hE[r][xx] = h;
            if (xx > 0) hO[r][xx - 1] = h;
        }
    }
    __syncthreads();

    const size_t rowoff = (size_t)(y0 + ri) * WW + xbase + xl;
    const __half* Ep = g_E + (size_t)(c * KK) * NPIX + (size_t)b * PLANE + rowoff;
    float* db = dst + (size_t)(b * CC + c) * PLANE;
    const __half2 Z2 = __float2half2_rn(0.f);

    __half2 accA[KQ], accB[KQ];
#pragma unroll
    for (int k = 0; k < KQ; k++) { accA[k] = Z2; accB[k] = Z2; }

#pragma unroll
    for (int dy = 0; dy < KQ; dy++) {
        __half2 tE[5], tO[4];
        {
            const uint2 a = *reinterpret_cast<const uint2*>(&hE[ri + dy][xl]);
            const uint2 bq = *reinterpret_cast<const uint2*>(&hE[ri + dy][xl + 4]);
            const unsigned int cq = *reinterpret_cast<const unsigned int*>(&hE[ri + dy][xl + 8]);
            *reinterpret_cast<unsigned int*>(&tE[0]) = a.x;
            *reinterpret_cast<unsigned int*>(&tE[1]) = a.y;
            *reinterpret_cast<unsigned int*>(&tE[2]) = bq.x;
            *reinterpret_cast<unsigned int*>(&tE[3]) = bq.y;
            *reinterpret_cast<unsigned int*>(&tE[4]) = cq;
            const uint2 d = *reinterpret_cast<const uint2*>(&hO[ri + dy][xl]);
            const uint2 e2 = *reinterpret_cast<const uint2*>(&hO[ri + dy][xl + 4]);
            *reinterpret_cast<unsigned int*>(&tO[0]) = d.x;
            *reinterpret_cast<unsigned int*>(&tO[1]) = d.y;
            *reinterpret_cast<unsigned int*>(&tO[2]) = e2.x;
            *reinterpret_cast<unsigned int*>(&tO[3]) = e2.y;
        }
#pragma unroll
        for (int dx = 0; dx < KQ; dx++) {
            const uint2 ev = *reinterpret_cast<const uint2*>(Ep + (size_t)(dy * KQ + dx) * NPIX);
            __half2 eA, eB;
            *reinterpret_cast<unsigned int*>(&eA) = ev.x;
            *reinterpret_cast<unsigned int*>(&eB) = ev.y;
            __half2 p1, p2;
            if ((dx & 1) == 0) { p1 = tE[dx >> 1]; p2 = tE[(dx >> 1) + 1]; }
            else               { p1 = tO[dx >> 1]; p2 = tO[(dx >> 1) + 1]; }
            accA[dx] = __hfma2(eA, p1, accA[dx]);
            accB[dx] = __hfma2(eB, p2, accB[dx]);
        }
    }
    __half2 rA0 = __hadd2(accA[0], accA[1]);
    __half2 rA1 = __hadd2(accA[2], accA[3]);
    __half2 rA2 = __hadd2(accA[4], accA[5]);
    __half2 rA3 = accA[6];
    __half2 rB0 = __hadd2(accB[0], accB[1]);
    __half2 rB1 = __hadd2(accB[2], accB[3]);
    __half2 rB2 = __hadd2(accB[4], accB[5]);
    __half2 rB3 = accB[6];
    const float2 fA0 = __half22float2(rA0), fA1 = __half22float2(rA1);
    const float2 fA2 = __half22float2(rA2), fA3 = __half22float2(rA3);
    const float2 fB0 = __half22float2(rB0), fB1 = __half22float2(rB1);
    const float2 fB2 = __half22float2(rB2), fB3 = __half22float2(rB3);
    float4 o;
    o.x = (fA0.x + fA1.x) + (fA2.x + fA3.x);
    o.y = (fA0.y + fA1.y) + (fA2.y + fA3.y);
    o.z = (fB0.x + fB1.x) + (fB2.x + fB3.x);
    o.w = (fB0.y + fB1.y) + (fB2.y + fB3.y);
    *reinterpret_cast<float4*>(db + rowoff) = o;     // raw (unnormalized)
}

// ================= K7: 1x1 conv (24 -> 1), applies final Sinv =================
__global__ void k_out(const float* __restrict__ w_td,
                      const float* __restrict__ b_td,
                      float* __restrict__ out) {
    const int bid = blockIdx.x;
    const int b = bid >> 8, y = bid & 255;
    const int tid = threadIdx.x;
    const size_t pix = (size_t)b * PLANE + (size_t)y * WW + tid;
    const float* sp = g_dB + (size_t)b * CC * PLANE + (size_t)y * WW + tid;
    float acc = 0.f;
#pragma unroll
    for (int c = 0; c < CC; c++) acc = fmaf(w_td[c], sp[(size_t)c * PLANE], acc);
    out[pix] = b_td[0] + acc * g_Sinv[pix];
}

// ================= host launcher =================
extern "C" void kernel_launch(void* const* d_in, const int* in_sizes, int n_in,
                              void* d_out, int out_size) {
    const float* depth   = (const float*)d_in[0];
    const float* texture = (const float*)d_in[1];
    const float* w_dp    = (const float*)d_in[2];
    const float* b_dp    = (const float*)d_in[3];
    const float* w_kp    = (const float*)d_in[4];
    const float* b_kp    = (const float*)d_in[5];
    const float* w_td    = (const float*)d_in[6];
    const float* b_td    = (const float*)d_in[7];
    float* out = (float*)d_out;

    k_lat<<<BB * HH, 256>>>(depth, w_dp, b_dp);

    // logits + exp + partial sums + FUSED iteration 1 (writes raw d1 to g_dA)
    dim3 gs(BB * HH / 2, CC);
    k_softmax<<<gs, 128>>>(texture, w_kp, b_kp);
    k_sinv<<<NPIX / 256, 256>>>();

    // iterations 2..4, L2-resident 6-channel groups
    dim3 gd(2 * HH / RROWS, GC, BB);
    for (int g = NGRP - 1; g >= 0; g--) {
        const int c0 = g * GC;
        k_diff<<<gd, 256>>>(1, 2, c0);   // dA -> dB  (iter 2)
        k_diff<<<gd, 256>>>(2, 1, c0);   // dB -> dA  (iter 3)
        k_diff<<<gd, 256>>>(1, 2, c0);   // dA -> dB  (iter 4)
    }

    k_out<<<BB * HH, 256>>>(w_td, b_td, out);
}

// round 16
// speedup vs baseline: 1.0779x; 1.0779x over previous
#include <cuda_runtime.h>
#include <cuda_fp16.h>
#include <cooperative_groups.h>
namespace cg = cooperative_groups;

// ---------------- problem constants ----------------
#define BB   2
#define CC   24
#define KQ   7
#define KK   49
#define HH   256
#define WW   256
#define CO   1176          // CC*KK
#define PLANE 65536
#define NPIX  131072

#define GC   6             // channels per L2-resident diffusion group (77MB < 126MB L2)
#define NGRP (CC / GC)     // 4 groups

#define LOG2E 1.4426950408889634f

// ---------------- device scratch ----------------
__device__ __half g_E[(size_t)CO * NPIX];   // unnormalized exp(logits), fp16, PLANE-MAJOR
__device__ float g_Spart[(size_t)CC * NPIX];
__device__ float g_Sinv[NPIX];
__device__ float g_lat[BB * CC * PLANE];
__device__ float g_dA[BB * CC * PLANE];     // raw (unnormalized) diffusion values
__device__ float g_dB[BB * CC * PLANE];

__device__ __forceinline__ float rcpf(float x) {
    float r; asm("rcp.approx.f32 %0, %1;" : "=f"(r) : "f"(x)); return r;
}
__device__ __forceinline__ __half2 ex2h2(__half2 x) {
    unsigned int xi = *reinterpret_cast<unsigned int*>(&x);
    unsigned int ri;
    asm("ex2.approx.f16x2 %0, %1;" : "=r"(ri) : "r"(xi));
    __half2 r;
    *reinterpret_cast<unsigned int*>(&r) = ri;
    return r;
}

// ================= K1: depth_latent = conv3x3(depth; 1 -> 24) =================
__global__ void k_lat(const float* __restrict__ depth,
                      const float* __restrict__ w_dp,
                      const float* __restrict__ b_dp) {
    __shared__ float sD[3][WW + 2];
    __shared__ float sW[CC * 9];
    __shared__ float sB[CC];
    const int bid = blockIdx.x;
    const int b = bid >> 8, y = bid & 255;
    const int tid = threadIdx.x;

    for (int i = tid; i < CC * 9; i += blockDim.x) sW[i] = w_dp[i];
    if (tid < CC) sB[tid] = b_dp[tid];

    const float* dp = depth + (size_t)b * PLANE;
    for (int r = 0; r < 3; r++) {
        const int yy = y + r - 1;
        for (int xx = tid; xx < WW + 2; xx += blockDim.x) {
            const int gx = xx - 1;
            sD[r][xx] = (yy >= 0 && yy < HH && gx >= 0 && gx < WW) ? dp[yy * WW + gx] : 0.f;
        }
    }
    __syncthreads();

    float p[9];
#pragma unroll
    for (int r = 0; r < 3; r++)
#pragma unroll
        for (int cx = 0; cx < 3; cx++) p[r * 3 + cx] = sD[r][tid + cx];

    for (int co = 0; co < CC; co++) {
        float acc = sB[co];
#pragma unroll
        for (int j = 0; j < 9; j++) acc = fmaf(sW[co * 9 + j], p[j], acc);
        g_lat[((size_t)(b * CC + co) * HH + y) * WW + tid] = acc;
    }
}

// ================= K2: logits conv + exp + partial sums + FUSED ITERATION 1 ==========
#define SR2 (WW + 12)
__global__ __launch_bounds__(128) void k_softmax(const float* __restrict__ tex,
                                                 const float* __restrict__ w_kp,
                                                 const float* __restrict__ b_kp) {
    __shared__ __align__(16) __half sWh[KK * 32];     // 27 weights + 5 zero-pad per output
    __shared__ __half2 sBh[KK];
    __shared__ __half sTh[3][4][WW + 2];
    __shared__ __align__(16) __half hL[10][SR2];      // lat rows y0-3..y0+6
    __shared__ __align__(16) __half hLO[10][SR2];     // hLO[r][xx] = hL[r][xx+1]

    const int bid = blockIdx.x;
    const int c = blockIdx.y;
    const int b = bid >> 7;
    const int y0 = (bid & 127) * 2;
    const int tid = threadIdx.x;
    const int ri = tid >> 6;
    const int x0 = (tid & 63) * 4;

    for (int i = tid; i < KK * 32; i += 128) {
        const int o = i >> 5, j = i & 31;
        const float w = (j < 27) ? w_kp[(size_t)(c * KK + o) * 27 + j] * LOG2E : 0.f;
        sWh[i] = __float2half_rn(w);
    }
    if (tid < KK) {
        const __half h = __float2half_rn(b_kp[c * KK + tid] * LOG2E);
        sBh[tid] = __halves2half2(h, h);
    }

    for (int ch = 0; ch < 3; ch++) {
        const float* tp = tex + (size_t)(b * 3 + ch) * PLANE;
        for (int rr = 0; rr < 4; rr++) {
            const int yy = y0 + rr - 1;
            for (int xx = tid; xx < WW + 2; xx += 128) {
                const int gx = xx - 1;
                const float v = (yy >= 0 && yy < HH && gx >= 0 && gx < WW) ? tp[yy * WW + gx] : 0.f;
                sTh[ch][rr][xx] = __float2half_rn(v);
            }
        }
    }

    {
        const float* lp = g_lat + (size_t)(b * CC + c) * PLANE;
        for (int r = 0; r < 10; r++) {
            const int yy = y0 + r - 3;
            for (int xx = tid; xx < WW + 8; xx += 128) {
                const int gx = xx - 3;
                const float v = (yy >= 0 && yy < HH && gx >= 0 && gx < WW) ? lp[yy * WW + gx] : 0.f;
                const __half h = __float2half_rn(v);
                hL[r][xx] = h;
                if (xx > 0) hLO[r][xx - 1] = h;
            }
        }
    }
    __syncthreads();

    __half2 PA[28], PB[28];
#pragma unroll
    for (int ch = 0; ch < 3; ch++)
#pragma unroll
        for (int r = 0; r < 3; r++) {
            __half v[6];
#pragma unroll
            for (int k = 0; k < 6; k++) v[k] = sTh[ch][ri + r][x0 + k];
#pragma unroll
            for (int cx = 0; cx < 3; cx++) {
                const int j = ch * 9 + r * 3 + cx;
                PA[j] = __halves2half2(v[cx], v[cx + 1]);
                PB[j] = __halves2half2(v[cx + 2], v[cx + 3]);
            }
        }
    PA[27] = __float2half2_rn(0.f);
    PB[27] = __float2half2_rn(0.f);

    float S0 = 0.f, S1 = 0.f, S2 = 0.f, S3 = 0.f;
    float dv0 = 0.f, dv1 = 0.f, dv2 = 0.f, dv3 = 0.f;
    const size_t pixbase = (size_t)b * PLANE + (size_t)(y0 + ri) * WW + x0;
    const __half2 Z2 = __float2half2_rn(0.f);

#pragma unroll 1
    for (int dx = 0; dx < KQ; dx++) {
        const __half* rowp = (dx & 1) ? &hLO[0][0] : &hL[0][0];
        const int xb = x0 + dx - (dx & 1);
        __half2 dacA = Z2, dacB = Z2;
#pragma unroll
        for (int dy = 0; dy < KQ; dy++) {
            const int ol = dy * KQ + dx;
            const uint4* wq = reinterpret_cast<const uint4*>(&sWh[ol * 32]);
            const __half2 bia = sBh[ol];
            __half2 wv[16];
            *reinterpret_cast<uint4*>(&wv[0])  = wq[0];
            *reinterpret_cast<uint4*>(&wv[4])  = wq[1];
            *reinterpret_cast<uint4*>(&wv[8])  = wq[2];
            *reinterpret_cast<uint4*>(&wv[12]) = wq[3];
            __half2 aA[4], aB[4];
            aA[0] = bia; aA[1] = Z2; aA[2] = Z2; aA[3] = Z2;
            aB[0] = bia; aB[1] = Z2; aB[2] = Z2; aB[3] = Z2;
#pragma unroll
            for (int j = 0; j < 28; j++) {
                const __half2 wj = (j & 1) ? __high2half2(wv[j >> 1]) : __low2half2(wv[j >> 1]);
                const int k = j & 3;
                aA[k] = __hfma2(wj, PA[j], aA[k]);
                aB[k] = __hfma2(wj, PB[j], aB[k]);
            }
            const __half2 a0 = __hadd2(__hadd2(aA[0], aA[1]), __hadd2(aA[2], aA[3]));
            const __half2 b0 = __hadd2(__hadd2(aB[0], aB[1]), __hadd2(aB[2], aB[3]));
            const __half2 eA = ex2h2(a0);
            const __half2 eB = ex2h2(b0);
            const float2 fA = __half22float2(eA);
            const float2 fB = __half22float2(eB);
            S0 += fA.x; S1 += fA.y; S2 += fB.x; S3 += fB.y;
            uint2 st;
            st.x = *reinterpret_cast<const unsigned int*>(&eA);
            st.y = *reinterpret_cast<const unsigned int*>(&eB);
            *reinterpret_cast<uint2*>(&g_E[(size_t)(c * KK + ol) * NPIX + pixbase]) = st;
            const __half* rp = rowp + (ri + dy) * SR2 + xb;
            __half2 p1, p2;
            *reinterpret_cast<unsigned int*>(&p1) = *reinterpret_cast<const unsigned int*>(rp);
            *reinterpret_cast<unsigned int*>(&p2) = *reinterpret_cast<const unsigned int*>(rp + 2);
            dacA = __hfma2(eA, p1, dacA);
            dacB = __hfma2(eB, p2, dacB);
        }
        const float2 fa = __half22float2(dacA);
        const float2 fb = __half22float2(dacB);
        dv0 += fa.x; dv1 += fa.y; dv2 += fb.x; dv3 += fb.y;
    }
    float4 ps;
    ps.x = S0; ps.y = S1; ps.z = S2; ps.w = S3;
    *reinterpret_cast<float4*>(&g_Spart[(size_t)c * NPIX + pixbase]) = ps;
    float4 dd;
    dd.x = dv0; dd.y = dv1; dd.z = dv2; dd.w = dv3;
    *reinterpret_cast<float4*>(&g_dA[(size_t)(b * CC + c) * PLANE + (size_t)(y0 + ri) * WW + x0]) = dd;
}

// ================= K2b: reduce 24 partials -> 1/S =================
__global__ void k_sinv() {
    const int idx = blockIdx.x * 256 + threadIdx.x;
    float s = 0.f;
#pragma unroll
    for (int c = 0; c < CC; c++) s += g_Spart[(size_t)c * NPIX + idx];
    g_Sinv[idx] = rcpf(s);
}

// ================= K3: iterations 2-4 for a 6-channel group, ONE cooperative launch =====
// grid (HH/8=32, GC=6, BB=2) = 384 blocks, 4/SM residency -> cooperative-legal.
// Per iteration: stage normalized src tile, compute 8x256, write raw dst; grid.sync.
#define RROWS 8
#define SROW  (WW + 12)
__global__ __launch_bounds__(256, 4) void k_diff3(int c0) {
    __shared__ __half hE[RROWS + 6][SROW];
    __shared__ __half hO[RROWS + 6][SROW];
    cg::grid_group grid = cg::this_grid();

    const int tid = threadIdx.x;
    const int ty = blockIdx.x;
    const int c = c0 + blockIdx.y;
    const int b = blockIdx.z;
    const int y0 = ty * RROWS;
    const int ri = tid >> 6;
    const int x0 = (tid & 63) * 4;
    const __half2 Z2 = __float2half2_rn(0.f);

    const __half* Eb = g_E + (size_t)(c * KK) * NPIX + (size_t)b * PLANE;
    const float* sip = g_Sinv + (size_t)b * PLANE;

#pragma unroll 1
    for (int it = 0; it < 3; it++) {
        const float* src = (it == 1) ? g_dB : g_dA;   // it0: dA, it1: dB, it2: dA
        float* dst = (it == 1) ? g_dA : g_dB;         // it0: dB, it1: dA, it2: dB

        const float* sp = src + (size_t)(b * CC + c) * PLANE;
        for (int r = 0; r < RROWS + 6; r++) {
            const int yy = y0 + r - 3;
            for (int xx = tid; xx < WW + 8; xx += 256) {
                const int gx = xx - 3;
                float v = 0.f;
                if (yy >= 0 && yy < HH && gx >= 0 && gx < WW) {
                    const int q = yy * WW + gx;
                    v = sp[q] * sip[q];          // deferred normalization at consumption
                }
                const __half h = __float2half_rn(v);
                hE[r][xx] = h;
                if (xx > 0) hO[r][xx - 1] = h;
            }
        }
        __syncthreads();

        float* db = dst + (size_t)(b * CC + c) * PLANE;

#pragma unroll
        for (int pass = 0; pass < 2; pass++) {
            const int ry = pass * 4 + ri;
            const size_t rowoff = (size_t)(y0 + ry) * WW + x0;
            const __half* Ep = Eb + rowoff;

            __half2 accA[KQ], accB[KQ];
#pragma unroll
            for (int k = 0; k < KQ; k++) { accA[k] = Z2; accB[k] = Z2; }

#pragma unroll
            for (int dy = 0; dy < KQ; dy++) {
                __half2 tE[5], tO[4];
                {
                    const uint2 a = *reinterpret_cast<const uint2*>(&hE[ry + dy][x0]);
                    const uint2 bq = *reinterpret_cast<const uint2*>(&hE[ry + dy][x0 + 4]);
                    const unsigned int cq = *reinterpret_cast<const unsigned int*>(&hE[ry + dy][x0 + 8]);
                    *reinterpret_cast<unsigned int*>(&tE[0]) = a.x;
                    *reinterpret_cast<unsigned int*>(&tE[1]) = a.y;
                    *reinterpret_cast<unsigned int*>(&tE[2]) = bq.x;
                    *reinterpret_cast<unsigned int*>(&tE[3]) = bq.y;
                    *reinterpret_cast<unsigned int*>(&tE[4]) = cq;
                    const uint2 d = *reinterpret_cast<const uint2*>(&hO[ry + dy][x0]);
                    const uint2 e2 = *reinterpret_cast<const uint2*>(&hO[ry + dy][x0 + 4]);
                    *reinterpret_cast<unsigned int*>(&tO[0]) = d.x;
                    *reinterpret_cast<unsigned int*>(&tO[1]) = d.y;
                    *reinterpret_cast<unsigned int*>(&tO[2]) = e2.x;
                    *reinterpret_cast<unsigned int*>(&tO[3]) = e2.y;
                }
#pragma unroll
                for (int dx = 0; dx < KQ; dx++) {
                    const uint2 ev = *reinterpret_cast<const uint2*>(Ep + (size_t)(dy * KQ + dx) * NPIX);
                    __half2 eA, eB;
                    *reinterpret_cast<unsigned int*>(&eA) = ev.x;
                    *reinterpret_cast<unsigned int*>(&eB) = ev.y;
                    __half2 p1, p2;
                    if ((dx & 1) == 0) { p1 = tE[dx >> 1]; p2 = tE[(dx >> 1) + 1]; }
                    else               { p1 = tO[dx >> 1]; p2 = tO[(dx >> 1) + 1]; }
                    accA[dx] = __hfma2(eA, p1, accA[dx]);
                    accB[dx] = __hfma2(eB, p2, accB[dx]);
                }
            }
            __half2 rA0 = __hadd2(accA[0], accA[1]);
            __half2 rA1 = __hadd2(accA[2], accA[3]);
            __half2 rA2 = __hadd2(accA[4], accA[5]);
            __half2 rA3 = accA[6];
            __half2 rB0 = __hadd2(accB[0], accB[1]);
            __half2 rB1 = __hadd2(accB[2], accB[3]);
            __half2 rB2 = __hadd2(accB[4], accB[5]);
            __half2 rB3 = accB[6];
            const float2 fA0 = __half22float2(rA0), fA1 = __half22float2(rA1);
            const float2 fA2 = __half22float2(rA2), fA3 = __half22float2(rA3);
            const float2 fB0 = __half22float2(rB0), fB1 = __half22float2(rB1);
            const float2 fB2 = __half22float2(rB2), fB3 = __half22float2(rB3);
            float4 o;
            o.x = (fA0.x + fA1.x) + (fA2.x + fA3.x);
            o.y = (fA0.y + fA1.y) + (fA2.y + fA3.y);
            o.z = (fB0.x + fB1.x) + (fB2.x + fB3.x);
            o.w = (fB0.y + fB1.y) + (fB2.y + fB3.y);
            *reinterpret_cast<float4*>(db + rowoff) = o;     // raw (unnormalized)
        }

        if (it < 2) {
            grid.sync();          // all blocks done with iteration `it` before next reads
            __syncthreads();
        }
    }
}

// ================= K7: 1x1 conv (24 -> 1), applies final Sinv =================
__global__ void k_out(const float* __restrict__ w_td,
                      const float* __restrict__ b_td,
                      float* __restrict__ out) {
    const int bid = blockIdx.x;
    const int b = bid >> 8, y = bid & 255;
    const int tid = threadIdx.x;
    const size_t pix = (size_t)b * PLANE + (size_t)y * WW + tid;
    const float* sp = g_dB + (size_t)b * CC * PLANE + (size_t)y * WW + tid;
    float acc = 0.f;
#pragma unroll
    for (int c = 0; c < CC; c++) acc = fmaf(w_td[c], sp[(size_t)c * PLANE], acc);
    out[pix] = b_td[0] + acc * g_Sinv[pix];
}

// ================= host launcher =================
extern "C" void kernel_launch(void* const* d_in, const int* in_sizes, int n_in,
                              void* d_out, int out_size) {
    const float* depth   = (const float*)d_in[0];
    const float* texture = (const float*)d_in[1];
    const float* w_dp    = (const float*)d_in[2];
    const float* b_dp    = (const float*)d_in[3];
    const float* w_kp    = (const float*)d_in[4];
    const float* b_kp    = (const float*)d_in[5];
    const float* w_td    = (const float*)d_in[6];
    const float* b_td    = (const float*)d_in[7];
    float* out = (float*)d_out;

    k_lat<<<BB * HH, 256>>>(depth, w_dp, b_dp);

    // logits + exp + partial sums + FUSED iteration 1 (writes raw d1 to g_dA)
    dim3 gs(BB * HH / 2, CC);
    k_softmax<<<gs, 128>>>(texture, w_kp, b_kp);
    k_sinv<<<NPIX / 256, 256>>>();

    // iterations 2..4: one cooperative launch per L2-resident 6-channel group
    dim3 gd(HH / RROWS, GC, BB);
    dim3 bd(256, 1, 1);
    for (int g = NGRP - 1; g >= 0; g--) {
        int c0 = g * GC;
        void* args[] = { &c0 };
        cudaLaunchCooperativeKernel((void*)k_diff3, gd, bd, args, 0, 0);
    }

    k_out<<<BB * HH, 256>>>(w_td, b_td, out);
}

// round 17
// speedup vs baseline: 1.0997x; 1.0202x over previous
#include <cuda_runtime.h>
#include <cuda_fp16.h>

// ---------------- problem constants ----------------
#define BB   2
#define CC   24
#define KQ   7
#define KK   49
#define HH   256
#define WW   256
#define CO   1176          // CC*KK
#define PLANE 65536
#define NPIX  131072

#define GC   6             // channels per L2-resident diffusion group (77MB < 126MB L2)
#define NGRP (CC / GC)     // 4 groups

#define LOG2E 1.4426950408889634f

// ---------------- device scratch ----------------
__device__ __half g_E[(size_t)CO * NPIX];   // unnormalized exp(logits), fp16, PLANE-MAJOR
__device__ float g_Spart[(size_t)CC * NPIX];
__device__ float g_Sinv[NPIX];
__device__ float g_lat[BB * CC * PLANE];
__device__ float g_dA[BB * CC * PLANE];     // raw (unnormalized) diffusion values
__device__ float g_dB[BB * CC * PLANE];

__device__ __forceinline__ float rcpf(float x) {
    float r; asm("rcp.approx.f32 %0, %1;" : "=f"(r) : "f"(x)); return r;
}
__device__ __forceinline__ __half2 ex2h2(__half2 x) {
    unsigned int xi = *reinterpret_cast<unsigned int*>(&x);
    unsigned int ri;
    asm("ex2.approx.f16x2 %0, %1;" : "=r"(ri) : "r"(xi));
    __half2 r;
    *reinterpret_cast<unsigned int*>(&r) = ri;
    return r;
}

// ================= K1: depth_latent = conv3x3(depth; 1 -> 24) =================
__global__ void k_lat(const float* __restrict__ depth,
                      const float* __restrict__ w_dp,
                      const float* __restrict__ b_dp) {
    __shared__ float sD[3][WW + 2];
    __shared__ float sW[CC * 9];
    __shared__ float sB[CC];
    const int bid = blockIdx.x;
    const int b = bid >> 8, y = bid & 255;
    const int tid = threadIdx.x;

    for (int i = tid; i < CC * 9; i += blockDim.x) sW[i] = w_dp[i];
    if (tid < CC) sB[tid] = b_dp[tid];

    const float* dp = depth + (size_t)b * PLANE;
    for (int r = 0; r < 3; r++) {
        const int yy = y + r - 1;
        for (int xx = tid; xx < WW + 2; xx += blockDim.x) {
            const int gx = xx - 1;
            sD[r][xx] = (yy >= 0 && yy < HH && gx >= 0 && gx < WW) ? dp[yy * WW + gx] : 0.f;
        }
    }
    __syncthreads();

    float p[9];
#pragma unroll
    for (int r = 0; r < 3; r++)
#pragma unroll
        for (int cx = 0; cx < 3; cx++) p[r * 3 + cx] = sD[r][tid + cx];

    for (int co = 0; co < CC; co++) {
        float acc = sB[co];
#pragma unroll
        for (int j = 0; j < 9; j++) acc = fmaf(sW[co * 9 + j], p[j], acc);
        g_lat[((size_t)(b * CC + co) * HH + y) * WW + tid] = acc;
    }
}

// ================= K2: logits conv + exp + partial sums + FUSED ITERATION 1 ==========
#define SR2 (WW + 12)
__global__ __launch_bounds__(128) void k_softmax(const float* __restrict__ tex,
                                                 const float* __restrict__ w_kp,
                                                 const float* __restrict__ b_kp) {
    __shared__ __align__(16) __half sWh[KK * 32];     // 27 weights + 5 zero-pad per output
    __shared__ __half2 sBh[KK];
    __shared__ __half sTh[3][4][WW + 2];
    __shared__ __align__(16) __half hL[10][SR2];      // lat rows y0-3..y0+6
    __shared__ __align__(16) __half hLO[10][SR2];     // hLO[r][xx] = hL[r][xx+1]

    const int bid = blockIdx.x;
    const int c = blockIdx.y;
    const int b = bid >> 7;
    const int y0 = (bid & 127) * 2;
    const int tid = threadIdx.x;
    const int ri = tid >> 6;
    const int x0 = (tid & 63) * 4;

    for (int i = tid; i < KK * 32; i += 128) {
        const int o = i >> 5, j = i & 31;
        const float w = (j < 27) ? w_kp[(size_t)(c * KK + o) * 27 + j] * LOG2E : 0.f;
        sWh[i] = __float2half_rn(w);
    }
    if (tid < KK) {
        const __half h = __float2half_rn(b_kp[c * KK + tid] * LOG2E);
        sBh[tid] = __halves2half2(h, h);
    }

    for (int ch = 0; ch < 3; ch++) {
        const float* tp = tex + (size_t)(b * 3 + ch) * PLANE;
        for (int rr = 0; rr < 4; rr++) {
            const int yy = y0 + rr - 1;
            for (int xx = tid; xx < WW + 2; xx += 128) {
                const int gx = xx - 1;
                const float v = (yy >= 0 && yy < HH && gx >= 0 && gx < WW) ? tp[yy * WW + gx] : 0.f;
                sTh[ch][rr][xx] = __float2half_rn(v);
            }
        }
    }

    {
        const float* lp = g_lat + (size_t)(b * CC + c) * PLANE;
        for (int r = 0; r < 10; r++) {
            const int yy = y0 + r - 3;
            for (int xx = tid; xx < WW + 8; xx += 128) {
                const int gx = xx - 3;
                const float v = (yy >= 0 && yy < HH && gx >= 0 && gx < WW) ? lp[yy * WW + gx] : 0.f;
                const __half h = __float2half_rn(v);
                hL[r][xx] = h;
                if (xx > 0) hLO[r][xx - 1] = h;
            }
        }
    }
    __syncthreads();

    __half2 PA[28], PB[28];
#pragma unroll
    for (int ch = 0; ch < 3; ch++)
#pragma unroll
        for (int r = 0; r < 3; r++) {
            __half v[6];
#pragma unroll
            for (int k = 0; k < 6; k++) v[k] = sTh[ch][ri + r][x0 + k];
#pragma unroll
            for (int cx = 0; cx < 3; cx++) {
                const int j = ch * 9 + r * 3 + cx;
                PA[j] = __halves2half2(v[cx], v[cx + 1]);
                PB[j] = __halves2half2(v[cx + 2], v[cx + 3]);
            }
        }
    PA[27] = __float2half2_rn(0.f);
    PB[27] = __float2half2_rn(0.f);

    float S0 = 0.f, S1 = 0.f, S2 = 0.f, S3 = 0.f;
    float dv0 = 0.f, dv1 = 0.f, dv2 = 0.f, dv3 = 0.f;
    const size_t pixbase = (size_t)b * PLANE + (size_t)(y0 + ri) * WW + x0;
    const __half2 Z2 = __float2half2_rn(0.f);

#pragma unroll 1
    for (int dx = 0; dx < KQ; dx++) {
        const __half* rowp = (dx & 1) ? &hLO[0][0] : &hL[0][0];
        const int xb = x0 + dx - (dx & 1);
        __half2 dacA = Z2, dacB = Z2;
#pragma unroll
        for (int dy = 0; dy < KQ; dy++) {
            const int ol = dy * KQ + dx;
            const uint4* wq = reinterpret_cast<const uint4*>(&sWh[ol * 32]);
            const __half2 bia = sBh[ol];
            __half2 wv[16];
            *reinterpret_cast<uint4*>(&wv[0])  = wq[0];
            *reinterpret_cast<uint4*>(&wv[4])  = wq[1];
            *reinterpret_cast<uint4*>(&wv[8])  = wq[2];
            *reinterpret_cast<uint4*>(&wv[12]) = wq[3];
            __half2 aA[4], aB[4];
            aA[0] = bia; aA[1] = Z2; aA[2] = Z2; aA[3] = Z2;
            aB[0] = bia; aB[1] = Z2; aB[2] = Z2; aB[3] = Z2;
#pragma unroll
            for (int j = 0; j < 28; j++) {
                const __half2 wj = (j & 1) ? __high2half2(wv[j >> 1]) : __low2half2(wv[j >> 1]);
                const int k = j & 3;
                aA[k] = __hfma2(wj, PA[j], aA[k]);
                aB[k] = __hfma2(wj, PB[j], aB[k]);
            }
            const __half2 a0 = __hadd2(__hadd2(aA[0], aA[1]), __hadd2(aA[2], aA[3]));
            const __half2 b0 = __hadd2(__hadd2(aB[0], aB[1]), __hadd2(aB[2], aB[3]));
            const __half2 eA = ex2h2(a0);
            const __half2 eB = ex2h2(b0);
            const float2 fA = __half22float2(eA);
            const float2 fB = __half22float2(eB);
            S0 += fA.x; S1 += fA.y; S2 += fB.x; S3 += fB.y;
            uint2 st;
            st.x = *reinterpret_cast<const unsigned int*>(&eA);
            st.y = *reinterpret_cast<const unsigned int*>(&eB);
            *reinterpret_cast<uint2*>(&g_E[(size_t)(c * KK + ol) * NPIX + pixbase]) = st;
            const __half* rp = rowp + (ri + dy) * SR2 + xb;
            __half2 p1, p2;
            *reinterpret_cast<unsigned int*>(&p1) = *reinterpret_cast<const unsigned int*>(rp);
            *reinterpret_cast<unsigned int*>(&p2) = *reinterpret_cast<const unsigned int*>(rp + 2);
            dacA = __hfma2(eA, p1, dacA);
            dacB = __hfma2(eB, p2, dacB);
        }
        const float2 fa = __half22float2(dacA);
        const float2 fb = __half22float2(dacB);
        dv0 += fa.x; dv1 += fa.y; dv2 += fb.x; dv3 += fb.y;
    }
    float4 ps;
    ps.x = S0; ps.y = S1; ps.z = S2; ps.w = S3;
    *reinterpret_cast<float4*>(&g_Spart[(size_t)c * NPIX + pixbase]) = ps;
    float4 dd;
    dd.x = dv0; dd.y = dv1; dd.z = dv2; dd.w = dv3;
    *reinterpret_cast<float4*>(&g_dA[(size_t)(b * CC + c) * PLANE + (size_t)(y0 + ri) * WW + x0]) = dd;
}

// ================= K2b: reduce 24 partials -> 1/S =================
__global__ void k_sinv() {
    const int idx = blockIdx.x * 256 + threadIdx.x;
    float s = 0.f;
#pragma unroll
    for (int c = 0; c < CC; c++) s += g_Spart[(size_t)c * NPIX + idx];
    g_Sinv[idx] = rcpf(s);
}

// ================= K3..: one diffusion iteration over a 6-channel group ==========
// 256 threads; thread handles 8 px (ri = tid>>5 row, xl = (tid&31)*8): E taps via
// LDG.128 (uint4 = 4 half2) -> 512B per warp-load, double outstanding bytes at MLP=7.
#define RROWS 8
#define SROW  272          // halves per row; 272*2=544 bytes, 16B multiple (LDS.128 align)
__global__ __launch_bounds__(256, 4) void k_diff(int srcSel, int dstSel, int c0) {
    __shared__ __align__(16) __half hE[RROWS + 6][SROW];
    __shared__ __align__(16) __half hO[RROWS + 6][SROW];
    const int tid = threadIdx.x;
    const int ty = blockIdx.x;
    const int c = c0 + blockIdx.y;
    const int b = blockIdx.z;
    const int y0 = ty * RROWS;
    const int ri = tid >> 5;                    // 0..7 (one row per thread-group)
    const int xl = (tid & 31) * 8;              // 8-px group base

    const float* src = (srcSel == 1) ? g_dA : g_dB;
    float* dst = (dstSel == 1) ? g_dA : g_dB;

    const float* sp = src + (size_t)(b * CC + c) * PLANE;
    const float* sip = g_Sinv + (size_t)b * PLANE;
    for (int r = 0; r < RROWS + 6; r++) {
        const int yy = y0 + r - 3;
        for (int xx = tid; xx < WW + 8; xx += 256) {
            const int gx = xx - 3;
            float v = 0.f;
            if (yy >= 0 && yy < HH && gx >= 0 && gx < WW) {
                const int q = yy * WW + gx;
                v = sp[q] * sip[q];          // deferred normalization at consumption
            }
            const __half h = __float2half_rn(v);
            hE[r][xx] = h;
            if (xx > 0) hO[r][xx - 1] = h;
        }
    }
    __syncthreads();

    const size_t rowoff = (size_t)(y0 + ri) * WW + xl;
    const __half* Ep = g_E + (size_t)(c * KK) * NPIX + (size_t)b * PLANE + rowoff;
    float* db = dst + (size_t)(b * CC + c) * PLANE;
    const __half2 Z2 = __float2half2_rn(0.f);

    // acc[dx][s]: stream s covers pixel pair (xl+2s, xl+2s+1)
    __half2 acc[KQ][4];
#pragma unroll
    for (int k = 0; k < KQ; k++)
#pragma unroll
        for (int s = 0; s < 4; s++) acc[k][s] = Z2;

#pragma unroll
    for (int dy = 0; dy < KQ; dy++) {
        // tE[j] = (xl+2j, xl+2j+1) j=0..6 ; tO[j] = (xl+2j+1, xl+2j+2) j=0..5
        __half2 tE[7], tO[6];
        {
            const uint4 a = *reinterpret_cast<const uint4*>(&hE[ri + dy][xl]);
            const uint2 bq = *reinterpret_cast<const uint2*>(&hE[ri + dy][xl + 8]);
            const unsigned int cq = *reinterpret_cast<const unsigned int*>(&hE[ri + dy][xl + 12]);
            *reinterpret_cast<unsigned int*>(&tE[0]) = a.x;
            *reinterpret_cast<unsigned int*>(&tE[1]) = a.y;
            *reinterpret_cast<unsigned int*>(&tE[2]) = a.z;
            *reinterpret_cast<unsigned int*>(&tE[3]) = a.w;
            *reinterpret_cast<unsigned int*>(&tE[4]) = bq.x;
            *reinterpret_cast<unsigned int*>(&tE[5]) = bq.y;
            *reinterpret_cast<unsigned int*>(&tE[6]) = cq;
            const uint4 d = *reinterpret_cast<const uint4*>(&hO[ri + dy][xl]);
            const uint2 e2 = *reinterpret_cast<const uint2*>(&hO[ri + dy][xl + 8]);
            *reinterpret_cast<unsigned int*>(&tO[0]) = d.x;
            *reinterpret_cast<unsigned int*>(&tO[1]) = d.y;
            *reinterpret_cast<unsigned int*>(&tO[2]) = d.z;
            *reinterpret_cast<unsigned int*>(&tO[3]) = d.w;
            *reinterpret_cast<unsigned int*>(&tO[4]) = e2.x;
            *reinterpret_cast<unsigned int*>(&tO[5]) = e2.y;
        }
#pragma unroll
        for (int dx = 0; dx < KQ; dx++) {
            const uint4 ev = *reinterpret_cast<const uint4*>(Ep + (size_t)(dy * KQ + dx) * NPIX);
            __half2 e0, e1, e2h, e3;
            *reinterpret_cast<unsigned int*>(&e0)  = ev.x;
            *reinterpret_cast<unsigned int*>(&e1)  = ev.y;
            *reinterpret_cast<unsigned int*>(&e2h) = ev.z;
            *reinterpret_cast<unsigned int*>(&e3)  = ev.w;
            if ((dx & 1) == 0) {
                const int h = dx >> 1;
                acc[dx][0] = __hfma2(e0,  tE[h],     acc[dx][0]);
                acc[dx][1] = __hfma2(e1,  tE[h + 1], acc[dx][1]);
                acc[dx][2] = __hfma2(e2h, tE[h + 2], acc[dx][2]);
                acc[dx][3] = __hfma2(e3,  tE[h + 3], acc[dx][3]);
            } else {
                const int h = dx >> 1;
                acc[dx][0] = __hfma2(e0,  tO[h],     acc[dx][0]);
                acc[dx][1] = __hfma2(e1,  tO[h + 1], acc[dx][1]);
                acc[dx][2] = __hfma2(e2h, tO[h + 2], acc[dx][2]);
                acc[dx][3] = __hfma2(e3,  tO[h + 3], acc[dx][3]);
            }
        }
    }

    // reduce per stream: 7 dx -> fp32
    float4 o0, o1;
    float* outp[8];
#pragma unroll
    for (int s = 0; s < 4; s++) {
        const __half2 r0 = __hadd2(acc[0][s], acc[1][s]);
        const __half2 r1 = __hadd2(acc[2][s], acc[3][s]);
        const __half2 r2 = __hadd2(acc[4][s], acc[5][s]);
        const __half2 r3 = acc[6][s];
        const float2 f0 = __half22float2(r0), f1 = __half22float2(r1);
        const float2 f2 = __half22float2(r2), f3 = __half22float2(r3);
        const float lo = (f0.x + f1.x) + (f2.x + f3.x);
        const float hi = (f0.y + f1.y) + (f2.y + f3.y);
        if (s == 0) { o0.x = lo; o0.y = hi; }
        else if (s == 1) { o0.z = lo; o0.w = hi; }
        else if (s == 2) { o1.x = lo; o1.y = hi; }
        else { o1.z = lo; o1.w = hi; }
    }
    (void)outp;
    *reinterpret_cast<float4*>(db + rowoff) = o0;        // raw (unnormalized)
    *reinterpret_cast<float4*>(db + rowoff + 4) = o1;
}

// ================= K7: 1x1 conv (24 -> 1), applies final Sinv =================
__global__ void k_out(const float* __restrict__ w_td,
                      const float* __restrict__ b_td,
                      float* __restrict__ out) {
    const int bid = blockIdx.x;
    const int b = bid >> 8, y = bid & 255;
    const int tid = threadIdx.x;
    const size_t pix = (size_t)b * PLANE + (size_t)y * WW + tid;
    const float* sp = g_dB + (size_t)b * CC * PLANE + (size_t)y * WW + tid;
    float acc = 0.f;
#pragma unroll
    for (int c = 0; c < CC; c++) acc = fmaf(w_td[c], sp[(size_t)c * PLANE], acc);
    out[pix] = b_td[0] + acc * g_Sinv[pix];
}

// ================= host launcher =================
extern "C" void kernel_launch(void* const* d_in, const int* in_sizes, int n_in,
                              void* d_out, int out_size) {
    const float* depth   = (const float*)d_in[0];
    const float* texture = (const float*)d_in[1];
    const float* w_dp    = (const float*)d_in[2];
    const float* b_dp    = (const float*)d_in[3];
    const float* w_kp    = (const float*)d_in[4];
    const float* b_kp    = (const float*)d_in[5];
    const float* w_td    = (const float*)d_in[6];
    const float* b_td    = (const float*)d_in[7];
    float* out = (float*)d_out;

    k_lat<<<BB * HH, 256>>>(depth, w_dp, b_dp);

    // logits + exp + partial sums + FUSED iteration 1 (writes raw d1 to g_dA)
    dim3 gs(BB * HH / 2, CC);
    k_softmax<<<gs, 128>>>(texture, w_kp, b_kp);
    k_sinv<<<NPIX / 256, 256>>>();

    // iterations 2..4, L2-resident 6-channel groups
    dim3 gd(HH / RROWS, GC, BB);
    for (int g = NGRP - 1; g >= 0; g--) {
        const int c0 = g * GC;
        k_diff<<<gd, 256>>>(1, 2, c0);   // dA -> dB  (iter 2)
        k_diff<<<gd, 256>>>(2, 1, c0);   // dB -> dA  (iter 3)
        k_diff<<<gd, 256>>>(1, 2, c0);   // dA -> dB  (iter 4)
    }

    k_out<<<BB * HH, 256>>>(w_td, b_td, out);
}